// round 12
// baseline (speedup 1.0000x reference)
#include <cuda_runtime.h>
#include <cstdint>

#define TSEQ   2048
#define MTOT   4096          // B*T
#define QKROW  1536          // q(1024) | k(256) | v(256)
#define NHEAD  16
#define NKV    4
#define HD     64

// Scratch (no allocation allowed): qkv activations and attention output.
__device__ float g_qkv[(size_t)MTOT * QKROW];
__device__ float g_y[(size_t)MTOT * 1024];

__device__ __forceinline__ float tf32r(float x) {
    uint32_t u;
    asm("cvt.rna.tf32.f32 %0, %1;" : "=r"(u) : "f"(x));
    return __uint_as_float(u);
}
__device__ __forceinline__ uint32_t tf32u(float x) {
    uint32_t u;
    asm("cvt.rna.tf32.f32 %0, %1;" : "=r"(u) : "f"(x));
    return u;
}

__device__ __forceinline__ void mma_tf32(float* d, const uint32_t* a, const uint32_t* b) {
    asm volatile(
        "mma.sync.aligned.m16n8k8.row.col.f32.tf32.tf32.f32 "
        "{%0,%1,%2,%3}, {%4,%5,%6,%7}, {%8,%9}, {%0,%1,%2,%3};\n"
        : "+f"(d[0]), "+f"(d[1]), "+f"(d[2]), "+f"(d[3])
        : "r"(a[0]), "r"(a[1]), "r"(a[2]), "r"(a[3]), "r"(b[0]), "r"(b[1]));
}

__device__ __forceinline__ void cpa16(float* dst, const float* src) {
    uint32_t s = (uint32_t)__cvta_generic_to_shared(dst);
    asm volatile("cp.async.cg.shared.global [%0], [%1], 16;\n" :: "r"(s), "l"(src));
}
__device__ __forceinline__ void cpa_commit() { asm volatile("cp.async.commit_group;\n"); }
__device__ __forceinline__ void cpa_wait0()  { asm volatile("cp.async.wait_group 0;\n" ::: "memory"); }

// ---------------------------------------------------------------------------
// TF32 GEMM (verified R11 version, unchanged). 128x256 block, 64x64 warp
// tiles, cp.async double-buffered; tf32 rounding at fragment load.
// ---------------------------------------------------------------------------
#define ASTRIDE 36
#define ABUF (128 * ASTRIDE)
#define BBUF (256 * ASTRIDE)
#define GBUF (ABUF + BBUF)
#define GSM_BYTES (2 * GBUF * 4)

__device__ __forceinline__
void gemm_body(const float* __restrict__ A, const float* __restrict__ B,
               float* __restrict__ C, int K, int ldc, int coff, int bm,
               float* __restrict__ sm)
{
    const int tid  = threadIdx.x;
    const int wid  = tid >> 5;
    const int lane = tid & 31;
    const int g    = lane >> 2;
    const int qid  = lane & 3;
    const int wm   = (wid >> 2) << 6;   // 0 or 64
    const int wn   = (wid & 3) << 6;    // 0,64,128,192

    float acc[4][8][4];
    #pragma unroll
    for (int mt = 0; mt < 4; mt++)
        #pragma unroll
        for (int nt = 0; nt < 8; nt++)
            #pragma unroll
            for (int r = 0; r < 4; r++) acc[mt][nt][r] = 0.f;

    const int KT = K >> 5;

    auto issue = [&](int kt, float* buf) {
        const float* Ag = A + (size_t)bm * K + (kt << 5);
        #pragma unroll
        for (int it = 0; it < 4; it++) {
            const int ca = tid + (it << 8);
            const int r = ca >> 3, ck = (ca & 7) << 2;
            cpa16(buf + r * ASTRIDE + ck, Ag + (size_t)r * K + ck);
        }
        const float* Bg = B + (kt << 5);
        float* bb = buf + ABUF;
        #pragma unroll
        for (int it = 0; it < 8; it++) {
            const int cb = tid + (it << 8);
            const int r = cb >> 3, ck = (cb & 7) << 2;
            cpa16(bb + r * ASTRIDE + ck, Bg + (size_t)r * K + ck);
        }
        cpa_commit();
    };

    issue(0, sm);
    for (int kt = 0; kt < KT; kt++) {
        cpa_wait0();
        __syncthreads();
        if (kt + 1 < KT) issue(kt + 1, sm + ((kt + 1) & 1) * GBUF);

        const float* As = sm + (kt & 1) * GBUF;
        const float* Bs = As + ABUF;

        #pragma unroll
        for (int kk = 0; kk < 32; kk += 8) {
            uint32_t af[4][4], bf[8][2];
            #pragma unroll
            for (int mt = 0; mt < 4; mt++) {
                const int m0 = wm + (mt << 4) + g;
                af[mt][0] = tf32u(As[(m0    ) * ASTRIDE + kk + qid]);
                af[mt][1] = tf32u(As[(m0 + 8) * ASTRIDE + kk + qid]);
                af[mt][2] = tf32u(As[(m0    ) * ASTRIDE + kk + qid + 4]);
                af[mt][3] = tf32u(As[(m0 + 8) * ASTRIDE + kk + qid + 4]);
            }
            #pragma unroll
            for (int nt = 0; nt < 8; nt++) {
                const int n0 = wn + (nt << 3) + g;
                bf[nt][0] = tf32u(Bs[n0 * ASTRIDE + kk + qid]);
                bf[nt][1] = tf32u(Bs[n0 * ASTRIDE + kk + qid + 4]);
            }
            #pragma unroll
            for (int mt = 0; mt < 4; mt++)
                #pragma unroll
                for (int nt = 0; nt < 8; nt++)
                    mma_tf32(acc[mt][nt], af[mt], bf[nt]);
        }
    }

    #pragma unroll
    for (int mt = 0; mt < 4; mt++) {
        const int r0 = bm + wm + (mt << 4) + g;
        #pragma unroll
        for (int nt = 0; nt < 8; nt++) {
            const int c0 = coff + wn + (nt << 3) + (qid << 1);
            *(float2*)&C[(size_t)r0 * ldc + c0] =
                make_float2(acc[mt][nt][0], acc[mt][nt][1]);
            *(float2*)&C[(size_t)(r0 + 8) * ldc + c0] =
                make_float2(acc[mt][nt][2], acc[mt][nt][3]);
        }
    }
}

// Fused QKV projection: grid (6, 32). 256-col block selects W segment.
__global__ __launch_bounds__(256, 1)
void gemm_qkv(const float* __restrict__ x, const float* __restrict__ Wq,
              const float* __restrict__ Wk, const float* __restrict__ Wv)
{
    extern __shared__ float gsm[];
    const int bx = blockIdx.x;          // 0..5, global col = bx*256
    const float* Bp;
    if (bx < 4)      Bp = Wq + (size_t)(bx << 8) * 1024;
    else if (bx == 4) Bp = Wk;
    else              Bp = Wv;
    gemm_body(x, Bp, g_qkv, 1024, QKROW, bx << 8, blockIdx.y << 7, gsm);
}

// Output projection: out = g_y @ Wo^T, grid (4, 32).
__global__ __launch_bounds__(256, 1)
void gemm_out(const float* __restrict__ Wo, float* __restrict__ out)
{
    extern __shared__ float gsm[];
    gemm_body(g_y, Wo + (size_t)(blockIdx.x << 8) * 1024, out,
              1024, 1024, blockIdx.x << 8, blockIdx.y << 7, gsm);
}

// ---------------------------------------------------------------------------
// Post-process (rotary+rmsnorm on q/k, gated ve add on v). Unchanged.
// ---------------------------------------------------------------------------
__global__ __launch_bounds__(768)
void postproc(const float* __restrict__ x, const float* __restrict__ ve,
              const float* __restrict__ cs, const float* __restrict__ sn,
              const float* __restrict__ Wg)
{
    const int row = blockIdx.x;            // b*T + t
    const int t = row & (TSEQ - 1);
    const int w = threadIdx.x >> 5;
    const int l = threadIdx.x & 31;
    float* base = g_qkv + (size_t)row * QKROW;

    if (w < 20) {
        const int off = (w < 16) ? (w << 6) : (1024 + ((w - 16) << 6));
        float x1 = base[off + l];
        float x2 = base[off + 32 + l];
        float c = cs[t * 32 + l];
        float s = sn[t * 32 + l];
        float a  = x1 * c + x2 * s;
        float bb = x2 * c - x1 * s;
        float ss = a * a + bb * bb;
        #pragma unroll
        for (int d = 16; d >= 1; d >>= 1) ss += __shfl_xor_sync(0xffffffffu, ss, d);
        float r = rsqrtf(ss * (1.0f / 64.0f) + 1.1920929e-7f) * 1.2f;
        base[off + l]      = a  * r;
        base[off + 32 + l] = bb * r;
    } else {
        const int kv = w - 20;
        float dot = (l < 12) ? x[(size_t)row * 1024 + l] * Wg[kv * 12 + l] : 0.f;
        #pragma unroll
        for (int d = 16; d >= 1; d >>= 1) dot += __shfl_xor_sync(0xffffffffu, dot, d);
        float g = 3.0f / (1.0f + __expf(-dot));
        const int off = 1280 + (kv << 6);
        const float* vep = ve + (size_t)row * 256 + (kv << 6);
        base[off + l]      += g * vep[l];
        base[off + 32 + l] += g * vep[32 + l];
    }
}

// ---------------------------------------------------------------------------
// Flash attention, TF32 tensor cores. BM=256 q-rows/block, 8 warps, each warp
// owns 32 q rows (2 m16 fragments) x full 64-key width -> K/V fragment loads
// are amortized over 2x the MACs vs the R9 version. Numerics (accumulation
// order, rounding points, reduction order per row) unchanged -> rel_err
// bit-identical. smem 141312 B: QP[256][68] | K0 V0 | K1 V1 (double buffer).
// ---------------------------------------------------------------------------
#define PADQ 68
#define PADK 68
#define PADV 72
#define OK0 (256 * PADQ)
#define OV0 (OK0 + 64 * PADK)
#define OK1 (OV0 + 64 * PADV)
#define OV1 (OK1 + 64 * PADK)
#define SM_FLOATS (OV1 + 64 * PADV)

__device__ __forceinline__
void load_kv_tile(const float* __restrict__ kptr, const float* __restrict__ vptr,
                  int k0, int tid, float* __restrict__ kd_base,
                  float* __restrict__ vd_base)
{
    const int r  = tid >> 2;
    const int c0 = (tid & 3) << 4;
    const float* ks = kptr + (size_t)(k0 + r) * QKROW + c0;
    const float* vs = vptr + (size_t)(k0 + r) * QKROW + c0;
    float* kd = kd_base + r * PADK + c0;
    float* vd = vd_base + r * PADV + c0;
    #pragma unroll
    for (int i = 0; i < 16; i += 4) {
        float4 k4 = *(const float4*)(ks + i);
        float4 v4 = *(const float4*)(vs + i);
        kd[i+0] = tf32r(k4.x); kd[i+1] = tf32r(k4.y);
        kd[i+2] = tf32r(k4.z); kd[i+3] = tf32r(k4.w);
        vd[i+0] = tf32r(v4.x); vd[i+1] = tf32r(v4.y);
        vd[i+2] = tf32r(v4.z); vd[i+3] = tf32r(v4.w);
    }
}

__global__ __launch_bounds__(256, 1)
void attn(const int* __restrict__ wlp)
{
    extern __shared__ float sm[];
    float* QP = sm;                 // Q tile, then P (exp scores)

    const int tid  = threadIdx.x;
    const int w    = tid >> 5;
    const int lane = tid & 31;
    const int g    = lane >> 2;
    const int qid  = lane & 3;
    const int qt = blockIdx.x;      // 0..7
    const int h  = blockIdx.y;      // 0..15
    const int b  = blockIdx.z;      // 0..1
    const int window = *wlp;
    const int kv = h >> 2;
    const int q0 = qt << 8;

    const float* rowbase = g_qkv + (size_t)b * TSEQ * QKROW;
    const float* qptr = rowbase + h * 64;
    const float* kptr = rowbase + 1024 + kv * 64;
    const float* vptr = rowbase + 1280 + kv * 64;

    {   // load Q tile (256 x 64): thread tid loads row tid (warp-private rows)
        const float* src = qptr + (size_t)(q0 + tid) * QKROW;
        float* dst = QP + tid * PADQ;
        #pragma unroll
        for (int i = 0; i < 64; i += 4) {
            float4 v4 = *(const float4*)(src + i);
            dst[i+0] = tf32r(v4.x); dst[i+1] = tf32r(v4.y);
            dst[i+2] = tf32r(v4.z); dst[i+3] = tf32r(v4.w);
        }
    }
    __syncwarp();

    const int mrow = (w << 5) + g;   // warp base row + group

    // Hoist Q fragments for both m-tiles to registers; QP then freed for P.
    uint32_t qf[2][8][4];
    #pragma unroll
    for (int mt = 0; mt < 2; mt++) {
        const int r0 = mrow + (mt << 4);
        #pragma unroll
        for (int k8 = 0; k8 < 8; k8++) {
            qf[mt][k8][0] = __float_as_uint(QP[(r0    ) * PADQ + (k8 << 3) + qid]);
            qf[mt][k8][1] = __float_as_uint(QP[(r0 + 8) * PADQ + (k8 << 3) + qid]);
            qf[mt][k8][2] = __float_as_uint(QP[(r0    ) * PADQ + (k8 << 3) + qid + 4]);
            qf[mt][k8][3] = __float_as_uint(QP[(r0 + 8) * PADQ + (k8 << 3) + qid + 4]);
        }
    }
    __syncwarp();

    float o[2][8][4];
    #pragma unroll
    for (int mt = 0; mt < 2; mt++)
        #pragma unroll
        for (int nt = 0; nt < 8; nt++)
            #pragma unroll
            for (int r = 0; r < 4; r++) o[mt][nt][r] = 0.f;
    float m[4], l[4];
    #pragma unroll
    for (int i = 0; i < 4; i++) { m[i] = -1e30f; l[i] = 0.f; }

    int lo = q0 - window; if (lo < 0) lo = 0;
    const int kt0 = lo >> 6;
    const int ktmax = (q0 + 255) >> 6;

    load_kv_tile(kptr, vptr, kt0 << 6, tid, sm + OK0, sm + OV0);
    __syncthreads();
    int p = 0;

    for (int kt = kt0; kt <= ktmax; kt++) {
        const int k0 = kt << 6;
        const float* Kc = sm + (p ? OK1 : OK0);
        const float* Vc = sm + (p ? OV1 : OV0);

        // ---- S = Q K^T (32 x 64 per warp; K-frags shared across m-tiles) ----
        float s[2][8][4];
        #pragma unroll
        for (int mt = 0; mt < 2; mt++)
            #pragma unroll
            for (int nt = 0; nt < 8; nt++)
                #pragma unroll
                for (int r = 0; r < 4; r++) s[mt][nt][r] = 0.f;
        #pragma unroll
        for (int k8 = 0; k8 < 8; k8++) {
            const int kk = k8 << 3;
            #pragma unroll
            for (int nt = 0; nt < 8; nt++) {
                uint32_t bfr[2];
                bfr[0] = __float_as_uint(Kc[((nt << 3) + g) * PADK + kk + qid]);
                bfr[1] = __float_as_uint(Kc[((nt << 3) + g) * PADK + kk + qid + 4]);
                mma_tf32(s[0][nt], qf[0][k8], bfr);
                mma_tf32(s[1][nt], qf[1][k8], bfr);
            }
        }

        // ---- mask + online softmax (warp-local rows, per m-tile) ----
        const bool interior = (k0 + 63 <= q0) && (q0 + 255 - k0 <= window);
        #pragma unroll
        for (int mt = 0; mt < 2; mt++) {
            const int qlo = q0 + mrow + (mt << 4);
            const int qhi = qlo + 8;
            float rx_lo = -1e30f, rx_hi = -1e30f;
            if (interior) {
                #pragma unroll
                for (int nt = 0; nt < 8; nt++) {
                    #pragma unroll
                    for (int c = 0; c < 2; c++) {
                        s[mt][nt][c]     *= 0.125f;
                        s[mt][nt][2 + c] *= 0.125f;
                        rx_lo = fmaxf(rx_lo, s[mt][nt][c]);
                        rx_hi = fmaxf(rx_hi, s[mt][nt][2 + c]);
                    }
                }
            } else {
                #pragma unroll
                for (int nt = 0; nt < 8; nt++) {
                    #pragma unroll
                    for (int c = 0; c < 2; c++) {
                        const int kj = k0 + (nt << 3) + (qid << 1) + c;
                        const bool ok_lo = (kj <= qlo) && (qlo - kj <= window);
                        const bool ok_hi = (kj <= qhi) && (qhi - kj <= window);
                        s[mt][nt][c]     = ok_lo ? s[mt][nt][c]     * 0.125f : -1e30f;
                        s[mt][nt][2 + c] = ok_hi ? s[mt][nt][2 + c] * 0.125f : -1e30f;
                        rx_lo = fmaxf(rx_lo, s[mt][nt][c]);
                        rx_hi = fmaxf(rx_hi, s[mt][nt][2 + c]);
                    }
                }
            }
            rx_lo = fmaxf(rx_lo, __shfl_xor_sync(0xffffffffu, rx_lo, 1));
            rx_lo = fmaxf(rx_lo, __shfl_xor_sync(0xffffffffu, rx_lo, 2));
            rx_hi = fmaxf(rx_hi, __shfl_xor_sync(0xffffffffu, rx_hi, 1));
            rx_hi = fmaxf(rx_hi, __shfl_xor_sync(0xffffffffu, rx_hi, 2));

            const float mn_lo = fmaxf(m[2*mt],     rx_lo);
            const float mn_hi = fmaxf(m[2*mt + 1], rx_hi);
            const float cr_lo = __expf(m[2*mt]     - mn_lo);
            const float cr_hi = __expf(m[2*mt + 1] - mn_hi);
            float rs_lo = 0.f, rs_hi = 0.f;
            const int r0 = mrow + (mt << 4);
            #pragma unroll
            for (int nt = 0; nt < 8; nt++) {
                float e0 = __expf(s[mt][nt][0] - mn_lo);
                float e1 = __expf(s[mt][nt][1] - mn_lo);
                float e2 = __expf(s[mt][nt][2] - mn_hi);
                float e3 = __expf(s[mt][nt][3] - mn_hi);
                rs_lo += e0 + e1;
                rs_hi += e2 + e3;
                const int pc = (nt << 3) + (qid << 1);
                *(float2*)&QP[(r0    ) * PADQ + pc] = make_float2(tf32r(e0), tf32r(e1));
                *(float2*)&QP[(r0 + 8) * PADQ + pc] = make_float2(tf32r(e2), tf32r(e3));
            }
            rs_lo += __shfl_xor_sync(0xffffffffu, rs_lo, 1);
            rs_lo += __shfl_xor_sync(0xffffffffu, rs_lo, 2);
            rs_hi += __shfl_xor_sync(0xffffffffu, rs_hi, 1);
            rs_hi += __shfl_xor_sync(0xffffffffu, rs_hi, 2);
            m[2*mt]     = mn_lo;
            m[2*mt + 1] = mn_hi;
            l[2*mt]     = l[2*mt]     * cr_lo + rs_lo;
            l[2*mt + 1] = l[2*mt + 1] * cr_hi + rs_hi;
            #pragma unroll
            for (int nt = 0; nt < 8; nt++) {
                o[mt][nt][0] *= cr_lo; o[mt][nt][1] *= cr_lo;
                o[mt][nt][2] *= cr_hi; o[mt][nt][3] *= cr_hi;
            }
        }
        __syncwarp();   // P rows visible across own warp's lanes

        // ---- O += P V (32 x 64 per warp; V-frags shared across m-tiles) ----
        #pragma unroll
        for (int k8 = 0; k8 < 8; k8++) {
            const int kk = k8 << 3;
            uint32_t a[2][4];
            #pragma unroll
            for (int mt = 0; mt < 2; mt++) {
                const int r0 = mrow + (mt << 4);
                a[mt][0] = __float_as_uint(QP[(r0    ) * PADQ + kk + qid]);
                a[mt][1] = __float_as_uint(QP[(r0 + 8) * PADQ + kk + qid]);
                a[mt][2] = __float_as_uint(QP[(r0    ) * PADQ + kk + qid + 4]);
                a[mt][3] = __float_as_uint(QP[(r0 + 8) * PADQ + kk + qid + 4]);
            }
            #pragma unroll
            for (int nt = 0; nt < 8; nt++) {
                uint32_t bfr[2];
                bfr[0] = __float_as_uint(Vc[(kk + qid    ) * PADV + (nt << 3) + g]);
                bfr[1] = __float_as_uint(Vc[(kk + qid + 4) * PADV + (nt << 3) + g]);
                mma_tf32(o[0][nt], a[0], bfr);
                mma_tf32(o[1][nt], a[1], bfr);
            }
        }
        __syncwarp();   // PV reads done before next tile's P overwrite

        // ---- prefetch next K/V tile into the other buffer ----
        if (kt < ktmax)
            load_kv_tile(kptr, vptr, (kt + 1) << 6, tid,
                         sm + (p ? OK0 : OK1), sm + (p ? OV0 : OV1));
        __syncthreads();
        p ^= 1;
    }

    #pragma unroll
    for (int mt = 0; mt < 2; mt++) {
        const float inv_lo = 1.0f / l[2*mt];
        const float inv_hi = 1.0f / l[2*mt + 1];
        const int r0 = q0 + mrow + (mt << 4);
        float* ylo = g_y + (size_t)(b * TSEQ + r0    ) * 1024 + h * 64;
        float* yhi = g_y + (size_t)(b * TSEQ + r0 + 8) * 1024 + h * 64;
        #pragma unroll
        for (int nt = 0; nt < 8; nt++) {
            const int c = (nt << 3) + (qid << 1);
            *(float2*)(ylo + c) = make_float2(o[mt][nt][0] * inv_lo, o[mt][nt][1] * inv_lo);
            *(float2*)(yhi + c) = make_float2(o[mt][nt][2] * inv_hi, o[mt][nt][3] * inv_hi);
        }
    }
}

// ---------------------------------------------------------------------------
extern "C" void kernel_launch(void* const* d_in, const int* in_sizes, int n_in,
                              void* d_out, int out_size)
{
    const float* x  = (const float*)d_in[0];
    const float* ve = (const float*)d_in[1];
    const float* cs = (const float*)d_in[2];
    const float* sn = (const float*)d_in[3];
    const float* Wq = (const float*)d_in[4];
    const float* Wk = (const float*)d_in[5];
    const float* Wv = (const float*)d_in[6];
    const float* Wo = (const float*)d_in[7];
    const float* Wg = (const float*)d_in[8];
    const int*   wl = (const int*)d_in[9];
    float* out = (float*)d_out;

    // Idempotent host-side calls; safe under graph capture, no static guards.
    cudaFuncSetAttribute(attn, cudaFuncAttributeMaxDynamicSharedMemorySize,
                         SM_FLOATS * sizeof(float));
    cudaFuncSetAttribute(gemm_qkv, cudaFuncAttributeMaxDynamicSharedMemorySize,
                         GSM_BYTES);
    cudaFuncSetAttribute(gemm_out, cudaFuncAttributeMaxDynamicSharedMemorySize,
                         GSM_BYTES);

    // Fused QKV projection -> g_qkv rows [q(1024) | k(256) | v(256)]
    gemm_qkv<<<dim3(6, 32), 256, GSM_BYTES>>>(x, Wq, Wk, Wv);

    // gate*ve add, rotary + rmsnorm * QK_SCALE
    postproc<<<MTOT, 768>>>(x, ve, cs, sn, Wg);

    // sliding-window flash attention (TF32 tensor cores) -> g_y
    attn<<<dim3(8, NHEAD, 2), 256, SM_FLOATS * sizeof(float)>>>(wl);

    // output projection: out = g_y @ Wo^T
    gemm_out<<<dim3(4, 32), 256, GSM_BYTES>>>(Wo, out);
}